// round 1
// baseline (speedup 1.0000x reference)
#include <cuda_runtime.h>
#include <cstdint>
#include <cstdio>

// ---------------- problem constants ----------------
#define BB_ 2
#define TT_ 2048
#define CC_ 1024
#define HH_ 16
#define DD_ 64
#define MTOT_ (BB_*TT_)          // 4096

// softmax uses base-2: exp(s/8) = 2^(s * log2(e)/8)
#define SOFTMAX_SCL 0.18033688011112042f

// ---------------- scratch (no allocations allowed) ----------------
__device__ float g_Q[BB_*HH_*TT_*DD_];   // [b,h,t,d]
__device__ float g_K[BB_*HH_*TT_*DD_];
__device__ float g_V[BB_*HH_*TT_*DD_];
__device__ float g_Yc[BB_*TT_*CC_];      // merged heads [b,t,c]

// ---------------- helpers ----------------
__device__ __forceinline__ unsigned f2tf(float x) {
    unsigned r;
    asm("cvt.rna.tf32.f32 %0, %1;" : "=r"(r) : "f"(x));
    return r;
}

__device__ __forceinline__ void mma8(float* d, const unsigned* a, const unsigned* b) {
    asm volatile(
        "mma.sync.aligned.m16n8k8.row.col.f32.tf32.tf32.f32 "
        "{%0,%1,%2,%3},{%4,%5,%6,%7},{%8,%9},{%0,%1,%2,%3};"
        : "+f"(d[0]), "+f"(d[1]), "+f"(d[2]), "+f"(d[3])
        : "r"(a[0]), "r"(a[1]), "r"(a[2]), "r"(a[3]),
          "r"(b[0]), "r"(b[1]));
}

// ============================================================================
// GEMM: C[m,n] = sum_k A[m,k] * B[n,k]   (torch-Linear "NT" gemm)
// Tiles: 128x128x32, 256 threads (8 warps as 2x4, warp tile 64x32).
// MODE 1: fused QKV — B selected among Wq/Wk/Wv by n; epilogue scatters to
//         g_Q/g_K/g_V in [b,h,t,d] layout.
// MODE 0: output projection — A is g_Yc (symbol), B0=Wo, writes Cout[m,n].
// K is fixed at 1024.
// ============================================================================
template<int MODE>
__global__ void __launch_bounds__(256) gemm_nt(
    const float* __restrict__ A,
    const float* __restrict__ B0, const float* __restrict__ B1,
    const float* __restrict__ B2,
    float* __restrict__ Cout)
{
    // padded to 36 words/row: (36 mod 32)==4 -> frag LDS hits 32 distinct banks
    __shared__ unsigned sA[128 * 36];
    __shared__ unsigned sB[128 * 36];

    const int tid  = threadIdx.x;
    const int bm   = blockIdx.y * 128;
    const int bn   = blockIdx.x * 128;
    const int warp = tid >> 5, lane = tid & 31;
    const int g = lane >> 2, t = lane & 3;
    const int wm = (warp & 1) * 64;     // warp m offset in tile
    const int wn = (warp >> 1) * 32;    // warp n offset in tile

    const float* Ause = A;
    const float* Bsel;
    int nloc, which = 0;
    if (MODE == 1) {
        which = bn >> 10;
        nloc  = bn & 1023;
        Bsel  = (which == 0) ? B0 : (which == 1) ? B1 : B2;
    } else {
        Ause = g_Yc;
        Bsel = B0;
        nloc = bn;
    }

    float acc[4][4][4];
    #pragma unroll
    for (int i = 0; i < 4; i++)
        #pragma unroll
        for (int j = 0; j < 4; j++)
            #pragma unroll
            for (int r = 0; r < 4; r++) acc[i][j][r] = 0.f;

    for (int k0 = 0; k0 < 1024; k0 += 32) {
        __syncthreads();
        // load A tile 128x32 (1024 float4, 4 per thread)
        #pragma unroll
        for (int i = 0; i < 4; i++) {
            int idx = tid + i * 256;
            int r = idx >> 3, c = (idx & 7) * 4;
            float4 v = *(const float4*)(Ause + (size_t)(bm + r) * 1024 + k0 + c);
            uint4 w = make_uint4(f2tf(v.x), f2tf(v.y), f2tf(v.z), f2tf(v.w));
            *(uint4*)&sA[r * 36 + c] = w;
        }
        // load B tile 128x32
        #pragma unroll
        for (int i = 0; i < 4; i++) {
            int idx = tid + i * 256;
            int r = idx >> 3, c = (idx & 7) * 4;
            float4 v = *(const float4*)(Bsel + (size_t)(nloc + r) * 1024 + k0 + c);
            uint4 w = make_uint4(f2tf(v.x), f2tf(v.y), f2tf(v.z), f2tf(v.w));
            *(uint4*)&sB[r * 36 + c] = w;
        }
        __syncthreads();

        #pragma unroll
        for (int ks = 0; ks < 32; ks += 8) {
            unsigned afr[4][4], bfr[4][2];
            #pragma unroll
            for (int im = 0; im < 4; im++) {
                int base = wm + im * 16;
                afr[im][0] = sA[(base + g    ) * 36 + ks + t    ];
                afr[im][1] = sA[(base + g + 8) * 36 + ks + t    ];
                afr[im][2] = sA[(base + g    ) * 36 + ks + t + 4];
                afr[im][3] = sA[(base + g + 8) * 36 + ks + t + 4];
            }
            #pragma unroll
            for (int in = 0; in < 4; in++) {
                int nb = wn + in * 8 + g;
                bfr[in][0] = sB[nb * 36 + ks + t    ];
                bfr[in][1] = sB[nb * 36 + ks + t + 4];
            }
            #pragma unroll
            for (int im = 0; im < 4; im++)
                #pragma unroll
                for (int in = 0; in < 4; in++)
                    mma8(acc[im][in], afr[im], bfr[in]);
        }
    }

    // ---------------- epilogue ----------------
    if (MODE == 0) {
        #pragma unroll
        for (int im = 0; im < 4; im++) {
            #pragma unroll
            for (int in = 0; in < 4; in++) {
                int r0 = bm + wm + im * 16 + g;
                int c0 = bn + wn + in * 8 + 2 * t;
                *(float2*)(Cout + (size_t)r0 * 1024 + c0) =
                    make_float2(acc[im][in][0], acc[im][in][1]);
                *(float2*)(Cout + (size_t)(r0 + 8) * 1024 + c0) =
                    make_float2(acc[im][in][2], acc[im][in][3]);
            }
        }
    } else {
        float* dst = (which == 0) ? g_Q : (which == 1) ? g_K : g_V;
        #pragma unroll
        for (int im = 0; im < 4; im++) {
            #pragma unroll
            for (int in = 0; in < 4; in++) {
                int r0 = bm + wm + im * 16 + g;         // m = b*2048 + t
                int b  = r0 >> 11, tt = r0 & 2047;      // 128-aligned tiles never cross b
                int n0 = nloc + wn + in * 8 + 2 * t;    // 0..1023
                int h  = n0 >> 6, d = n0 & 63;
                size_t base = ((size_t)(b * HH_ + h) * TT_);
                *(float2*)(dst + (base + tt    ) * DD_ + d) =
                    make_float2(acc[im][in][0], acc[im][in][1]);
                *(float2*)(dst + (base + tt + 8) * DD_ + d) =
                    make_float2(acc[im][in][2], acc[im][in][3]);
            }
        }
    }
}

// ============================================================================
// Flash attention (causal), one block = 64 q-rows of one (b,h).
// 4 warps, each warp owns 16 q-rows. K/V tiles of 64 rows streamed.
// TF32 mma for S=QK^T and O+=P V; fp32 online softmax; P via SMEM.
// ============================================================================
#define ATTN_SMEM_WORDS (64*68*3 + 64*72)
#define ATTN_SMEM_BYTES (ATTN_SMEM_WORDS * 4)

__global__ void __launch_bounds__(128) attn_kernel()
{
    extern __shared__ unsigned smem_u[];
    unsigned* sQ = smem_u;               // [64][68]
    unsigned* sK = sQ + 64 * 68;         // [64][68]
    unsigned* sP = sK + 64 * 68;         // [64][68]
    unsigned* sV = sP + 64 * 68;         // [64][72]  (stride%32==8 for k-major frags)

    const int bh = blockIdx.y;                        // b*16 + h
    const int qt = gridDim.x - 1 - blockIdx.x;        // biggest tiles first
    const int q0 = qt * 64;

    const float* Qp = g_Q + (size_t)bh * TT_ * DD_;
    const float* Kp = g_K + (size_t)bh * TT_ * DD_;
    const float* Vp = g_V + (size_t)bh * TT_ * DD_;

    const int tid = threadIdx.x;
    const int warp = tid >> 5, lane = tid & 31;
    const int g = lane >> 2, t = lane & 3;

    // load Q tile once (64x64 floats)
    #pragma unroll
    for (int i = 0; i < 8; i++) {
        int idx = tid + i * 128;
        int r = idx >> 4, c = (idx & 15) * 4;
        float4 v = *(const float4*)(Qp + (size_t)(q0 + r) * DD_ + c);
        uint4 w = make_uint4(f2tf(v.x), f2tf(v.y), f2tf(v.z), f2tf(v.w));
        *(uint4*)&sQ[r * 68 + c] = w;
    }

    float m0 = -INFINITY, m1 = -INFINITY;   // row maxima (log2 domain)
    float l0 = 0.f, l1 = 0.f;               // row sums
    float o[8][4];
    #pragma unroll
    for (int i = 0; i < 8; i++)
        #pragma unroll
        for (int r = 0; r < 4; r++) o[i][r] = 0.f;

    const int rq0 = q0 + warp * 16 + g;
    const int rq1 = rq0 + 8;

    for (int kt = 0; kt <= q0; kt += 64) {
        __syncthreads();   // everyone done with previous sK/sV (and Q stores visible)
        #pragma unroll
        for (int i = 0; i < 8; i++) {
            int idx = tid + i * 128;
            int r = idx >> 4, c = (idx & 15) * 4;
            float4 kv = *(const float4*)(Kp + (size_t)(kt + r) * DD_ + c);
            *(uint4*)&sK[r * 68 + c] =
                make_uint4(f2tf(kv.x), f2tf(kv.y), f2tf(kv.z), f2tf(kv.w));
            float4 vv = *(const float4*)(Vp + (size_t)(kt + r) * DD_ + c);
            *(uint4*)&sV[r * 72 + c] =
                make_uint4(f2tf(vv.x), f2tf(vv.y), f2tf(vv.z), f2tf(vv.w));
        }
        __syncthreads();

        // ---- S = Q K^T (warp: 16 q-rows x 64 k-cols) ----
        float s[8][4];
        #pragma unroll
        for (int in = 0; in < 8; in++)
            #pragma unroll
            for (int r = 0; r < 4; r++) s[in][r] = 0.f;

        #pragma unroll
        for (int ks = 0; ks < 64; ks += 8) {
            unsigned a[4];
            int base = warp * 16;
            a[0] = sQ[(base + g    ) * 68 + ks + t    ];
            a[1] = sQ[(base + g + 8) * 68 + ks + t    ];
            a[2] = sQ[(base + g    ) * 68 + ks + t + 4];
            a[3] = sQ[(base + g + 8) * 68 + ks + t + 4];
            #pragma unroll
            for (int in = 0; in < 8; in++) {
                unsigned b[2];
                int nb = in * 8 + g;
                b[0] = sK[nb * 68 + ks + t    ];
                b[1] = sK[nb * 68 + ks + t + 4];
                mma8(s[in], a, b);
            }
        }

        // ---- scale, causal mask, row max ----
        const bool diag = (kt == q0);
        float mx0 = -INFINITY, mx1 = -INFINITY;
        #pragma unroll
        for (int in = 0; in < 8; in++) {
            int c = kt + in * 8 + 2 * t;
            float x0 = s[in][0] * SOFTMAX_SCL;
            float x1 = s[in][1] * SOFTMAX_SCL;
            float x2 = s[in][2] * SOFTMAX_SCL;
            float x3 = s[in][3] * SOFTMAX_SCL;
            if (diag) {
                if (c     > rq0) x0 = -INFINITY;
                if (c + 1 > rq0) x1 = -INFINITY;
                if (c     > rq1) x2 = -INFINITY;
                if (c + 1 > rq1) x3 = -INFINITY;
            }
            s[in][0] = x0; s[in][1] = x1; s[in][2] = x2; s[in][3] = x3;
            mx0 = fmaxf(mx0, fmaxf(x0, x1));
            mx1 = fmaxf(mx1, fmaxf(x2, x3));
        }
        mx0 = fmaxf(mx0, __shfl_xor_sync(0xffffffffu, mx0, 1));
        mx0 = fmaxf(mx0, __shfl_xor_sync(0xffffffffu, mx0, 2));
        mx1 = fmaxf(mx1, __shfl_xor_sync(0xffffffffu, mx1, 1));
        mx1 = fmaxf(mx1, __shfl_xor_sync(0xffffffffu, mx1, 2));

        float nm0 = fmaxf(m0, mx0), nm1 = fmaxf(m1, mx1);
        float cor0 = exp2f(m0 - nm0), cor1 = exp2f(m1 - nm1);
        m0 = nm0; m1 = nm1;

        // ---- P = exp2(x - m), row sums, stage P to SMEM as tf32 ----
        float sum0 = 0.f, sum1 = 0.f;
        #pragma unroll
        for (int in = 0; in < 8; in++) {
            float p0 = exp2f(s[in][0] - nm0);
            float p1 = exp2f(s[in][1] - nm0);
            float p2 = exp2f(s[in][2] - nm1);
            float p3 = exp2f(s[in][3] - nm1);
            sum0 += p0 + p1;
            sum1 += p2 + p3;
            int cl = in * 8 + 2 * t;
            int r0l = warp * 16 + g;
            sP[ r0l      * 68 + cl    ] = f2tf(p0);
            sP[ r0l      * 68 + cl + 1] = f2tf(p1);
            sP[(r0l + 8) * 68 + cl    ] = f2tf(p2);
            sP[(r0l + 8) * 68 + cl + 1] = f2tf(p3);
        }
        sum0 += __shfl_xor_sync(0xffffffffu, sum0, 1);
        sum0 += __shfl_xor_sync(0xffffffffu, sum0, 2);
        sum1 += __shfl_xor_sync(0xffffffffu, sum1, 1);
        sum1 += __shfl_xor_sync(0xffffffffu, sum1, 2);
        l0 = l0 * cor0 + sum0;
        l1 = l1 * cor1 + sum1;

        // rescale running O
        #pragma unroll
        for (int in = 0; in < 8; in++) {
            o[in][0] *= cor0; o[in][1] *= cor0;
            o[in][2] *= cor1; o[in][3] *= cor1;
        }
        __syncwarp();   // sP is per-warp private rows; warp-level visibility is enough

        // ---- O += P V ----
        #pragma unroll
        for (int ks = 0; ks < 64; ks += 8) {
            unsigned a[4];
            int base = warp * 16;
            a[0] = sP[(base + g    ) * 68 + ks + t    ];
            a[1] = sP[(base + g + 8) * 68 + ks + t    ];
            a[2] = sP[(base + g    ) * 68 + ks + t + 4];
            a[3] = sP[(base + g + 8) * 68 + ks + t + 4];
            #pragma unroll
            for (int in = 0; in < 8; in++) {
                unsigned b[2];
                b[0] = sV[(ks + t    ) * 72 + in * 8 + g];
                b[1] = sV[(ks + t + 4) * 72 + in * 8 + g];
                mma8(o[in], a, b);
            }
        }
        __syncwarp();
    }

    // ---- normalize and write merged-head output ----
    const float inv0 = 1.f / l0, inv1 = 1.f / l1;
    const int b = bh >> 4, h = bh & 15;
    #pragma unroll
    for (int in = 0; in < 8; in++) {
        int dcol = in * 8 + 2 * t;
        int r0 = q0 + warp * 16 + g;
        size_t base0 = ((size_t)(b * TT_ + r0)     * CC_) + h * DD_ + dcol;
        size_t base1 = ((size_t)(b * TT_ + r0 + 8) * CC_) + h * DD_ + dcol;
        *(float2*)(g_Yc + base0) = make_float2(o[in][0] * inv0, o[in][1] * inv0);
        *(float2*)(g_Yc + base1) = make_float2(o[in][2] * inv1, o[in][3] * inv1);
    }
}

// ============================================================================
// launch
// ============================================================================
extern "C" void kernel_launch(void* const* d_in, const int* in_sizes, int n_in,
                              void* d_out, int out_size)
{
    const float* X  = (const float*)d_in[0];
    const float* Wq = (const float*)d_in[1];
    const float* Wk = (const float*)d_in[2];
    const float* Wv = (const float*)d_in[3];
    const float* Wo = (const float*)d_in[4];
    float* out = (float*)d_out;

    cudaFuncSetAttribute(attn_kernel,
                         cudaFuncAttributeMaxDynamicSharedMemorySize,
                         ATTN_SMEM_BYTES);

    // QKV: M=4096, N=3072 (Wq|Wk|Wv), K=1024
    gemm_nt<1><<<dim3(24, 32), 256>>>(X, Wq, Wk, Wv, nullptr);

    // attention: grid = (q-tiles=32, b*h=32)
    attn_kernel<<<dim3(32, 32), 128, ATTN_SMEM_BYTES>>>();

    // output projection: M=4096, N=1024, K=1024 (A = g_Yc internally)
    gemm_nt<0><<<dim3(8, 32), 256>>>(nullptr, Wo, nullptr, nullptr, out);
}